// round 14
// baseline (speedup 1.0000x reference)
#include <cuda_runtime.h>
#include <cuda_fp16.h>
#include <cstdint>

// Problem dims
#define K_DIM 8192
#define N_DIM 8192

// GEMM tiling: CTA_N=128 kept; 4 fat warps (WARP_N=32) to halve A re-reads.
#define KSPLIT 4
#define KCHUNK (K_DIM / KSPLIT)          // 2048
#define NKSTEPS (KCHUNK / 16)            // 128 k-steps of 16
#define CTA_N 128
#define NSTRIPS (N_DIM / CTA_N)          // 64
#define THREADS 128
#define WARPS 4
#define WARP_N 32                        // 4 n-tiles of 8 per warp
#define STAGES 5

// Shared-memory stage layout
#define W_ROW_BYTES (CTA_N * 4)                  // 512
#define W_ROW_STRIDE (W_ROW_BYTES + 16)          // 528 (pad -> conflict-free frag LDS)
#define W_STAGE_BYTES (16 * W_ROW_STRIDE)        // 8448
#define A_STAGE_BYTES 1024                       // 2 t-tiles * 32 lanes * 16B
#define STAGE_BYTES (W_STAGE_BYTES + A_STAGE_BYTES)  // 9472
#define SMEM_BYTES (STAGES * STAGE_BYTES)        // 47360 (< 48KB static limit)

// Scratch (allocation-free: __device__ globals)
__device__ __align__(16) __half g_Apack[32 * K_DIM];     // 512 KB, fragment-packed A
__device__ __align__(16) float g_Yp[KSPLIT][32 * N_DIM]; // 4 MB partials

// ---------------------------------------------------------------------------
// Kernel 1: fold scaler into x, fp16, fragment-pack A.
// One thread per 4B slot (131072 threads) -> latency-bound fix.
// 16B line L: ks = L>>6, t = (L>>5)&1, lane = L&31 (g = lane>>2, tg = lane&3)
// slot s in line: row = t*16+g + 8*(s&1), k = ks*16 + tg*2 + 8*(s>>1).
// ---------------------------------------------------------------------------
__global__ void prep_pack_kernel(const float* __restrict__ x,
                                 const float* __restrict__ scaler) {
    int L4 = blockIdx.x * blockDim.x + threadIdx.x;  // 0 .. 131071
    float s = scaler[0];
    int line = L4 >> 2;
    int slot = L4 & 3;
    int ks   = line >> 6;
    int rem  = line & 63;
    int t    = rem >> 5;
    int lane = rem & 31;
    int g  = lane >> 2;
    int tg = lane & 3;
    int r = t * 16 + g + ((slot & 1) << 3);
    int k = ks * 16 + tg * 2 + ((slot >> 1) << 3);

    float2 v = *reinterpret_cast<const float2*>(&x[(size_t)r * K_DIM + k]);
    __half2 h = __floats2half2_rn(v.x * s, v.y * s);   // low = even k
    reinterpret_cast<unsigned*>(g_Apack)[L4] = *reinterpret_cast<unsigned*>(&h);
}

// ---------------------------------------------------------------------------
// Kernel 2: cp.async-pipelined fused dequant GEMM (mma m16n8k16 f16.f32).
// CTA: 128 n-cols, 4 warps (warp_n = 32, m = 32). 5-stage static-smem pipeline.
// ---------------------------------------------------------------------------
__global__ __launch_bounds__(THREADS, 4) void gemm_kernel(const int* __restrict__ W) {
    __shared__ __align__(16) char sm[SMEM_BYTES];

    const int tid  = threadIdx.x;
    const int lane = tid & 31;
    const int warp = tid >> 5;
    const int g    = lane >> 2;
    const int tg   = lane & 3;

    const int n0cta = blockIdx.x * CTA_N;
    const int krow0 = blockIdx.y * KCHUNK;     // first k row of this split
    const int ks0   = blockIdx.y * NKSTEPS;    // first global kstep (for A pack)

    // cp.async thread coords: 512 W granules of 16B per stage, 128 threads -> 4 each
    // (rows wr + 4j, col granule c16). Threads [0,64) also copy one 16B A granule.
    const int wr  = tid >> 5;                  // 0..3
    const int c16 = tid & 31;                  // 16B column granule within row
    const char* wsrc0 = (const char*)(W + (size_t)(krow0 + wr) * N_DIM + n0cta + c16 * 4);
    const char* asrc0 = (const char*)g_Apack + (size_t)ks0 * A_STAGE_BYTES + tid * 16;
    const unsigned sm_base = (unsigned)__cvta_generic_to_shared(sm);

    auto issue_stage = [&](int p) {
        if (p < NKSTEPS) {
            unsigned d  = sm_base + (p % STAGES) * STAGE_BYTES;
            const char* ws = wsrc0 + (size_t)p * 16 * N_DIM * 4;
            unsigned d0 = d + wr * W_ROW_STRIDE + c16 * 16;
            #pragma unroll
            for (int j = 0; j < 4; j++) {
                asm volatile("cp.async.cg.shared.global [%0], [%1], 16;\n"
                             :: "r"(d0 + j * 4 * W_ROW_STRIDE),
                                "l"(ws + (size_t)j * 4 * N_DIM * 4));
            }
            if (tid < 64) {
                asm volatile("cp.async.ca.shared.global [%0], [%1], 16;\n"
                             :: "r"(d + W_STAGE_BYTES + tid * 16),
                                "l"(asrc0 + (size_t)p * A_STAGE_BYTES));
            }
        }
        asm volatile("cp.async.commit_group;\n" ::);
    };

    issue_stage(0);
    issue_stage(1);
    issue_stage(2);
    issue_stage(3);

    float acc[2][4][4] = {};

    for (int ks = 0; ks < NKSTEPS; ks++) {
        asm volatile("cp.async.wait_group 3;\n" ::);
        __syncthreads();
        issue_stage(ks + 4);   // refills the buffer consumed at iteration ks-1

        const unsigned sb = sm_base + (ks % STAGES) * STAGE_BYTES;

        // A fragments: 2 x LDS.128 (broadcast across the 4 warps)
        unsigned a[2][4];
        const unsigned ab = sb + W_STAGE_BYTES + lane * 16;
        #pragma unroll
        for (int t = 0; t < 2; t++) {
            asm volatile("ld.shared.v4.b32 {%0,%1,%2,%3}, [%4];"
                         : "=r"(a[t][0]), "=r"(a[t][1]), "=r"(a[t][2]), "=r"(a[t][3])
                         : "r"(ab + t * 512));
        }

        #pragma unroll
        for (int i = 0; i < 4; i++) {
            // B ints from smem: rows tg*2 + {0,1,8,9}, col warp*32 + i*8 + g.
            // Row stride 528B -> bank = (8*tg + 8*i + g) mod 32 : conflict-free.
            const unsigned wb = sb + (tg * 2) * W_ROW_STRIDE + (warp * WARP_N + i * 8 + g) * 4;
            int w0, w1, w2, w3;
            asm volatile("ld.shared.b32 %0, [%1];" : "=r"(w0) : "r"(wb));
            asm volatile("ld.shared.b32 %0, [%1];" : "=r"(w1) : "r"(wb + W_ROW_STRIDE));
            asm volatile("ld.shared.b32 %0, [%1];" : "=r"(w2) : "r"(wb + 8 * W_ROW_STRIDE));
            asm volatile("ld.shared.b32 %0, [%1];" : "=r"(w3) : "r"(wb + 9 * W_ROW_STRIDE));
            __half2 p0 = __floats2half2_rn((float)w0, (float)w1);   // low = even k
            __half2 p1 = __floats2half2_rn((float)w2, (float)w3);
            unsigned b0 = *reinterpret_cast<unsigned*>(&p0);
            unsigned b1 = *reinterpret_cast<unsigned*>(&p1);

            #pragma unroll
            for (int t = 0; t < 2; t++) {
                float* c = acc[t][i];
                asm volatile(
                    "mma.sync.aligned.m16n8k16.row.col.f32.f16.f16.f32 "
                    "{%0,%1,%2,%3}, {%4,%5,%6,%7}, {%8,%9}, {%0,%1,%2,%3};"
                    : "+f"(c[0]), "+f"(c[1]), "+f"(c[2]), "+f"(c[3])
                    : "r"(a[t][0]), "r"(a[t][1]), "r"(a[t][2]), "r"(a[t][3]),
                      "r"(b0), "r"(b1));
            }
        }
    }

    // Epilogue: fp32 partials
    float* yp = g_Yp[blockIdx.y];
    #pragma unroll
    for (int t = 0; t < 2; t++) {
        #pragma unroll
        for (int i = 0; i < 4; i++) {
            const int row = t * 16 + g;
            const int col = n0cta + warp * WARP_N + i * 8 + tg * 2;
            *reinterpret_cast<float2*>(&yp[(size_t)row * N_DIM + col]) =
                make_float2(acc[t][i][0], acc[t][i][1]);
            *reinterpret_cast<float2*>(&yp[(size_t)(row + 8) * N_DIM + col]) =
                make_float2(acc[t][i][2], acc[t][i][3]);
        }
    }
}

// ---------------------------------------------------------------------------
// Kernel 3: reduce k-splits (float4).
// ---------------------------------------------------------------------------
__global__ void reduce_kernel(float* __restrict__ out) {
    int idx4 = blockIdx.x * blockDim.x + threadIdx.x;   // 0 .. 32*2048-1
    float4 s = make_float4(0.f, 0.f, 0.f, 0.f);
    #pragma unroll
    for (int sp = 0; sp < KSPLIT; sp++) {
        float4 v = reinterpret_cast<const float4*>(g_Yp[sp])[idx4];
        s.x += v.x; s.y += v.y; s.z += v.z; s.w += v.w;
    }
    reinterpret_cast<float4*>(out)[idx4] = s;
}

// ---------------------------------------------------------------------------
extern "C" void kernel_launch(void* const* d_in, const int* in_sizes, int n_in,
                              void* d_out, int out_size) {
    const float* x      = (const float*)d_in[0];   // [32, 8192] fp32
    const int*   w      = (const int*)d_in[1];     // [8192, 8192] int32 (int8-valued)
    const float* scaler = (const float*)d_in[2];   // [1] fp32
    float* out = (float*)d_out;                    // [32, 8192] fp32

    prep_pack_kernel<<<512, 256>>>(x, scaler);
    gemm_kernel<<<dim3(NSTRIPS, KSPLIT), THREADS>>>(w);
    reduce_kernel<<<128, 512>>>(out);
}

// round 15
// speedup vs baseline: 1.1187x; 1.1187x over previous
#include <cuda_runtime.h>
#include <cuda_fp16.h>
#include <cstdint>

// Problem dims
#define K_DIM 8192
#define N_DIM 8192

// GEMM tiling (R11 shape; finer k-split for wave balance)
#define KSPLIT 16
#define KCHUNK (K_DIM / KSPLIT)          // 512
#define NKSTEPS (KCHUNK / 16)            // 32 k-steps of 16
#define CTA_N 128
#define NSTRIPS (N_DIM / CTA_N)          // 64
#define WARPS 8
#define WARP_N 16                        // 2 n-tiles of 8 per warp
#define STAGES 6                         // paired k-steps: 2 consumed per barrier

// Shared-memory stage layout
#define W_ROW_BYTES (CTA_N * 4)                  // 512
#define W_ROW_STRIDE (W_ROW_BYTES + 16)          // 528 (pad -> conflict-free frag LDS)
#define W_STAGE_BYTES (16 * W_ROW_STRIDE)        // 8448
#define A_STAGE_BYTES 1024                       // 2 t-tiles * 32 lanes * 16B
#define STAGE_BYTES (W_STAGE_BYTES + A_STAGE_BYTES)  // 9472
#define SMEM_BYTES (STAGES * STAGE_BYTES)        // 56832 (dynamic)

// Scratch (allocation-free: __device__ globals)
__device__ __align__(16) __half g_Apack[32 * K_DIM];     // 512 KB, fragment-packed A
__device__ __align__(16) float g_Yp[KSPLIT][32 * N_DIM]; // 16 MB partials

// ---------------------------------------------------------------------------
// Kernel 1: fold scaler into x, fp16, fragment-pack A (R11-best variant).
// One thread per 8B half-line (2 slots).
// ---------------------------------------------------------------------------
__global__ void prep_pack_kernel(const float* __restrict__ x,
                                 const float* __restrict__ scaler) {
    int L8 = blockIdx.x * blockDim.x + threadIdx.x;  // 0 .. 65535
    float s = scaler[0];
    int line = L8 >> 1;
    int half = L8 & 1;
    int ks   = line >> 6;
    int rem  = line & 63;
    int t    = rem >> 5;
    int lane = rem & 31;
    int g  = lane >> 2;
    int tg = lane & 3;
    int r0 = t * 16 + g;
    int k  = ks * 16 + tg * 2 + half * 8;

    float2 v0 = *reinterpret_cast<const float2*>(&x[(size_t)r0 * K_DIM + k]);
    float2 v1 = *reinterpret_cast<const float2*>(&x[(size_t)(r0 + 8) * K_DIM + k]);
    __half2 h0 = __floats2half2_rn(v0.x * s, v0.y * s);   // low = even k
    __half2 h1 = __floats2half2_rn(v1.x * s, v1.y * s);

    uint2 o;
    o.x = *reinterpret_cast<unsigned*>(&h0);
    o.y = *reinterpret_cast<unsigned*>(&h1);
    reinterpret_cast<uint2*>(g_Apack)[L8] = o;
}

// ---------------------------------------------------------------------------
// Kernel 2: cp.async-pipelined fused dequant GEMM (mma m16n8k16 f16.f32).
// CTA: 128 n-cols, 8 warps (warp_n = 16, m = 32). 6-stage pipeline,
// 2 k-steps consumed per barrier. 1024 CTAs of 32 k-steps each.
// ---------------------------------------------------------------------------
__global__ __launch_bounds__(256, 2) void gemm_kernel(const int* __restrict__ W) {
    extern __shared__ __align__(16) char sm[];

    const int tid  = threadIdx.x;
    const int lane = tid & 31;
    const int warp = tid >> 5;
    const int g    = lane >> 2;
    const int tg   = lane & 3;

    const int n0cta = blockIdx.x * CTA_N;
    const int krow0 = blockIdx.y * KCHUNK;     // first k row of this split
    const int ks0   = blockIdx.y * NKSTEPS;    // first global kstep (for A pack)

    // cp.async thread coords: each thread copies two 16B W granules;
    // threads [0,64) also copy one 16B A granule.
    const int r0  = tid >> 5;                  // W tile row 0..7 (and +8)
    const int c16 = tid & 31;                  // 16B column granule within row
    const char* wsrc0 = (const char*)(W + (size_t)(krow0 + r0) * N_DIM + n0cta + c16 * 4);
    const char* asrc0 = (const char*)g_Apack + (size_t)ks0 * A_STAGE_BYTES + tid * 16;
    const unsigned sm_base = (unsigned)__cvta_generic_to_shared(sm);

    auto issue_stage = [&](int p) {
        if (p < NKSTEPS) {
            unsigned d  = sm_base + (p % STAGES) * STAGE_BYTES;
            const char* ws = wsrc0 + (size_t)p * 16 * N_DIM * 4;
            unsigned d0 = d + r0 * W_ROW_STRIDE + c16 * 16;
            asm volatile("cp.async.cg.shared.global [%0], [%1], 16;\n"
                         :: "r"(d0), "l"(ws));
            asm volatile("cp.async.cg.shared.global [%0], [%1], 16;\n"
                         :: "r"(d0 + 8 * W_ROW_STRIDE), "l"(ws + (size_t)8 * N_DIM * 4));
            if (tid < 64) {
                asm volatile("cp.async.ca.shared.global [%0], [%1], 16;\n"
                             :: "r"(d + W_STAGE_BYTES + tid * 16),
                                "l"(asrc0 + (size_t)p * A_STAGE_BYTES));
            }
        }
        asm volatile("cp.async.commit_group;\n" ::);
    };

    issue_stage(0);
    issue_stage(1);
    issue_stage(2);
    issue_stage(3);

    float acc[2][2][4] = {};

    auto consume = [&](int ks) {
        const unsigned sb = sm_base + (ks % STAGES) * STAGE_BYTES;

        // A fragments: 2 x LDS.128 (broadcast across warps)
        unsigned a[2][4];
        const unsigned ab = sb + W_STAGE_BYTES + lane * 16;
        #pragma unroll
        for (int t = 0; t < 2; t++) {
            asm volatile("ld.shared.v4.b32 {%0,%1,%2,%3}, [%4];"
                         : "=r"(a[t][0]), "=r"(a[t][1]), "=r"(a[t][2]), "=r"(a[t][3])
                         : "r"(ab + t * 512));
        }

        #pragma unroll
        for (int i = 0; i < 2; i++) {
            // B ints from smem: rows tg*2 + {0,1,8,9}, col warp*16 + i*8 + g.
            // Row stride 528B -> bank = 8*tg + g (+const) : conflict-free.
            const unsigned wb = sb + (tg * 2) * W_ROW_STRIDE + (warp * WARP_N + i * 8 + g) * 4;
            int w0, w1, w2, w3;
            asm volatile("ld.shared.b32 %0, [%1];" : "=r"(w0) : "r"(wb));
            asm volatile("ld.shared.b32 %0, [%1];" : "=r"(w1) : "r"(wb + W_ROW_STRIDE));
            asm volatile("ld.shared.b32 %0, [%1];" : "=r"(w2) : "r"(wb + 8 * W_ROW_STRIDE));
            asm volatile("ld.shared.b32 %0, [%1];" : "=r"(w3) : "r"(wb + 9 * W_ROW_STRIDE));
            __half2 p0 = __floats2half2_rn((float)w0, (float)w1);   // low = even k
            __half2 p1 = __floats2half2_rn((float)w2, (float)w3);
            unsigned b0 = *reinterpret_cast<unsigned*>(&p0);
            unsigned b1 = *reinterpret_cast<unsigned*>(&p1);

            #pragma unroll
            for (int t = 0; t < 2; t++) {
                float* c = acc[t][i];
                asm volatile(
                    "mma.sync.aligned.m16n8k16.row.col.f32.f16.f16.f32 "
                    "{%0,%1,%2,%3}, {%4,%5,%6,%7}, {%8,%9}, {%0,%1,%2,%3};"
                    : "+f"(c[0]), "+f"(c[1]), "+f"(c[2]), "+f"(c[3])
                    : "r"(a[t][0]), "r"(a[t][1]), "r"(a[t][2]), "r"(a[t][3]),
                      "r"(b0), "r"(b1));
            }
        }
    };

    for (int ks = 0; ks < NKSTEPS; ks += 2) {
        // Need stages ks, ks+1 complete; 2 newer groups may stay in flight.
        asm volatile("cp.async.wait_group 2;\n" ::);
        __syncthreads();
        issue_stage(ks + 4);
        issue_stage(ks + 5);
        consume(ks);
        consume(ks + 1);
    }

    // Epilogue: fp32 partials
    float* yp = g_Yp[blockIdx.y];
    #pragma unroll
    for (int t = 0; t < 2; t++) {
        #pragma unroll
        for (int i = 0; i < 2; i++) {
            const int row = t * 16 + g;
            const int col = n0cta + warp * WARP_N + i * 8 + tg * 2;
            *reinterpret_cast<float2*>(&yp[(size_t)row * N_DIM + col]) =
                make_float2(acc[t][i][0], acc[t][i][1]);
            *reinterpret_cast<float2*>(&yp[(size_t)(row + 8) * N_DIM + col]) =
                make_float2(acc[t][i][2], acc[t][i][3]);
        }
    }
}

// ---------------------------------------------------------------------------
// Kernel 3: reduce k-splits (float4).
// ---------------------------------------------------------------------------
__global__ void reduce_kernel(float* __restrict__ out) {
    int idx4 = blockIdx.x * blockDim.x + threadIdx.x;   // 0 .. 32*2048-1
    float4 s = make_float4(0.f, 0.f, 0.f, 0.f);
    #pragma unroll
    for (int sp = 0; sp < KSPLIT; sp++) {
        float4 v = reinterpret_cast<const float4*>(g_Yp[sp])[idx4];
        s.x += v.x; s.y += v.y; s.z += v.z; s.w += v.w;
    }
    reinterpret_cast<float4*>(out)[idx4] = s;
}

// ---------------------------------------------------------------------------
extern "C" void kernel_launch(void* const* d_in, const int* in_sizes, int n_in,
                              void* d_out, int out_size) {
    const float* x      = (const float*)d_in[0];   // [32, 8192] fp32
    const int*   w      = (const int*)d_in[1];     // [8192, 8192] int32 (int8-valued)
    const float* scaler = (const float*)d_in[2];   // [1] fp32
    float* out = (float*)d_out;                    // [32, 8192] fp32

    static bool attr_set = false;
    if (!attr_set) {
        cudaFuncSetAttribute(gemm_kernel,
                             cudaFuncAttributeMaxDynamicSharedMemorySize, SMEM_BYTES);
        attr_set = true;
    }

    prep_pack_kernel<<<256, 256>>>(x, scaler);
    gemm_kernel<<<dim3(NSTRIPS, KSPLIT), 256, SMEM_BYTES>>>(w);
    reduce_kernel<<<128, 512>>>(out);
}

// round 16
// speedup vs baseline: 1.3678x; 1.2226x over previous
#include <cuda_runtime.h>
#include <cuda_fp16.h>
#include <cstdint>

// Problem dims
#define K_DIM 8192
#define N_DIM 8192

// GEMM tiling (R11-best shape)
#define KSPLIT 4
#define KCHUNK (K_DIM / KSPLIT)          // 2048
#define NKSTEPS (KCHUNK / 16)            // 128 k-steps of 16
#define CTA_N 128
#define NSTRIPS (N_DIM / CTA_N)          // 64
#define WARPS 8
#define WARP_N 16                        // 2 n-tiles of 8 per warp
#define STAGES 6                         // paired k-steps: 2 consumed per barrier

// Shared-memory stage layout (W only; A now goes via registers from L2)
#define W_ROW_BYTES (CTA_N * 4)                  // 512
#define W_ROW_STRIDE (W_ROW_BYTES + 16)          // 528 (pad -> conflict-free frag LDS)
#define STAGE_BYTES (16 * W_ROW_STRIDE)          // 8448
#define SMEM_BYTES (STAGES * STAGE_BYTES)        // 50688 (dynamic)

// Scratch (allocation-free: __device__ globals)
// A packed per kstep: 1024B = [t(2)][lane(32)][16B], fragment-register order.
__device__ __align__(16) __half g_Apack[32 * K_DIM];     // 512 KB (L2-resident)
__device__ __align__(16) float g_Yp[KSPLIT][32 * N_DIM]; // 4 MB partials

// ---------------------------------------------------------------------------
// Kernel 1: fold scaler into x, fp16, fragment-pack A (R11-best variant).
// ---------------------------------------------------------------------------
__global__ void prep_pack_kernel(const float* __restrict__ x,
                                 const float* __restrict__ scaler) {
    int L8 = blockIdx.x * blockDim.x + threadIdx.x;  // 0 .. 65535
    float s = scaler[0];
    int line = L8 >> 1;
    int half = L8 & 1;
    int ks   = line >> 6;
    int rem  = line & 63;
    int t    = rem >> 5;
    int lane = rem & 31;
    int g  = lane >> 2;
    int tg = lane & 3;
    int r0 = t * 16 + g;
    int k  = ks * 16 + tg * 2 + half * 8;

    float2 v0 = *reinterpret_cast<const float2*>(&x[(size_t)r0 * K_DIM + k]);
    float2 v1 = *reinterpret_cast<const float2*>(&x[(size_t)(r0 + 8) * K_DIM + k]);
    __half2 h0 = __floats2half2_rn(v0.x * s, v0.y * s);   // low = even k
    __half2 h1 = __floats2half2_rn(v1.x * s, v1.y * s);

    uint2 o;
    o.x = *reinterpret_cast<unsigned*>(&h0);
    o.y = *reinterpret_cast<unsigned*>(&h1);
    reinterpret_cast<uint2*>(g_Apack)[L8] = o;
}

// ---------------------------------------------------------------------------
// Kernel 2: cp.async-pipelined fused dequant GEMM (mma m16n8k16 f16.f32).
// W: 6-stage smem pipeline (2 k-steps per barrier). A: register double-buffer
// prefetched from L2-resident g_Apack with coalesced LDG.128.
// ---------------------------------------------------------------------------
__global__ __launch_bounds__(256, 2) void gemm_kernel(const int* __restrict__ W) {
    extern __shared__ __align__(16) char sm[];

    const int tid  = threadIdx.x;
    const int lane = tid & 31;
    const int warp = tid >> 5;
    const int g    = lane >> 2;
    const int tg   = lane & 3;

    const int n0cta = blockIdx.x * CTA_N;
    const int krow0 = blockIdx.y * KCHUNK;     // first k row of this split
    const int ks0   = blockIdx.y * NKSTEPS;    // first global kstep (for A pack)

    // cp.async thread coords: each thread copies two 16B W granules.
    const int r0  = tid >> 5;                  // W tile row 0..7 (and +8)
    const int c16 = tid & 31;                  // 16B column granule within row
    const char* wsrc0 = (const char*)(W + (size_t)(krow0 + r0) * N_DIM + n0cta + c16 * 4);
    const unsigned sm_base = (unsigned)__cvta_generic_to_shared(sm);

    auto issue_stage = [&](int p) {
        if (p < NKSTEPS) {
            unsigned d  = sm_base + (p % STAGES) * STAGE_BYTES;
            const char* ws = wsrc0 + (size_t)p * 16 * N_DIM * 4;
            unsigned d0 = d + r0 * W_ROW_STRIDE + c16 * 16;
            asm volatile("cp.async.cg.shared.global [%0], [%1], 16;\n"
                         :: "r"(d0), "l"(ws));
            asm volatile("cp.async.cg.shared.global [%0], [%1], 16;\n"
                         :: "r"(d0 + 8 * W_ROW_STRIDE), "l"(ws + (size_t)8 * N_DIM * 4));
        }
        asm volatile("cp.async.commit_group;\n" ::);
    };

    // A fragment loader: per k-step, per warp: 2 x LDG.128 (coalesced 512B x2).
    const char* abase = (const char*)g_Apack + (size_t)ks0 * 1024 + lane * 16;
    auto ldA = [&](int ks, uint4* dst) {
        const char* p = abase + (size_t)ks * 1024;
        dst[0] = *reinterpret_cast<const uint4*>(p);
        dst[1] = *reinterpret_cast<const uint4*>(p + 512);
    };

    issue_stage(0);
    issue_stage(1);
    issue_stage(2);
    issue_stage(3);

    float acc[2][2][4] = {};

    auto consume = [&](int ks, const uint4* af) {
        const unsigned sb = sm_base + (ks % STAGES) * STAGE_BYTES;
        unsigned a[2][4];
        #pragma unroll
        for (int t = 0; t < 2; t++) {
            a[t][0] = af[t].x; a[t][1] = af[t].y;
            a[t][2] = af[t].z; a[t][3] = af[t].w;
        }

        #pragma unroll
        for (int i = 0; i < 2; i++) {
            // B ints from smem: rows tg*2 + {0,1,8,9}, col warp*16 + i*8 + g.
            // Row stride 528B -> bank = 8*tg + g (+const) : conflict-free.
            const unsigned wb = sb + (tg * 2) * W_ROW_STRIDE + (warp * WARP_N + i * 8 + g) * 4;
            int w0, w1, w2, w3;
            asm volatile("ld.shared.b32 %0, [%1];" : "=r"(w0) : "r"(wb));
            asm volatile("ld.shared.b32 %0, [%1];" : "=r"(w1) : "r"(wb + W_ROW_STRIDE));
            asm volatile("ld.shared.b32 %0, [%1];" : "=r"(w2) : "r"(wb + 8 * W_ROW_STRIDE));
            asm volatile("ld.shared.b32 %0, [%1];" : "=r"(w3) : "r"(wb + 9 * W_ROW_STRIDE));
            __half2 p0 = __floats2half2_rn((float)w0, (float)w1);   // low = even k
            __half2 p1 = __floats2half2_rn((float)w2, (float)w3);
            unsigned b0 = *reinterpret_cast<unsigned*>(&p0);
            unsigned b1 = *reinterpret_cast<unsigned*>(&p1);

            #pragma unroll
            for (int t = 0; t < 2; t++) {
                float* c = acc[t][i];
                asm volatile(
                    "mma.sync.aligned.m16n8k16.row.col.f32.f16.f16.f32 "
                    "{%0,%1,%2,%3}, {%4,%5,%6,%7}, {%8,%9}, {%0,%1,%2,%3};"
                    : "+f"(c[0]), "+f"(c[1]), "+f"(c[2]), "+f"(c[3])
                    : "r"(a[t][0]), "r"(a[t][1]), "r"(a[t][2]), "r"(a[t][3]),
                      "r"(b0), "r"(b1));
            }
        }
    };

    // A double-buffer: aC holds k-steps {ks, ks+1}, aN holds {ks+2, ks+3}.
    uint4 aC[2][2], aN[2][2];
    ldA(0, aC[0]);
    ldA(1, aC[1]);

    // NKSTEPS = 128, divisible by 4: unroll two pair-iterations to ping-pong regs.
    for (int ks = 0; ks < NKSTEPS; ks += 4) {
        // pair 1: consume ks, ks+1 from aC; prefetch ks+2, ks+3 into aN.
        asm volatile("cp.async.wait_group 2;\n" ::);
        __syncthreads();
        issue_stage(ks + 4);
        issue_stage(ks + 5);
        ldA(ks + 2, aN[0]);
        ldA(ks + 3, aN[1]);
        consume(ks,     aC[0]);
        consume(ks + 1, aC[1]);

        // pair 2: consume ks+2, ks+3 from aN; prefetch ks+4, ks+5 into aC.
        asm volatile("cp.async.wait_group 2;\n" ::);
        __syncthreads();
        issue_stage(ks + 6);
        issue_stage(ks + 7);
        int p4 = (ks + 4 < NKSTEPS) ? ks + 4 : NKSTEPS - 1;
        int p5 = (ks + 5 < NKSTEPS) ? ks + 5 : NKSTEPS - 1;
        ldA(p4, aC[0]);
        ldA(p5, aC[1]);
        consume(ks + 2, aN[0]);
        consume(ks + 3, aN[1]);
    }

    // Epilogue: fp32 partials
    float* yp = g_Yp[blockIdx.y];
    #pragma unroll
    for (int t = 0; t < 2; t++) {
        #pragma unroll
        for (int i = 0; i < 2; i++) {
            const int row = t * 16 + g;
            const int col = n0cta + warp * WARP_N + i * 8 + tg * 2;
            *reinterpret_cast<float2*>(&yp[(size_t)row * N_DIM + col]) =
                make_float2(acc[t][i][0], acc[t][i][1]);
            *reinterpret_cast<float2*>(&yp[(size_t)(row + 8) * N_DIM + col]) =
                make_float2(acc[t][i][2], acc[t][i][3]);
        }
    }
}

// ---------------------------------------------------------------------------
// Kernel 3: reduce k-splits (float4).
// ---------------------------------------------------------------------------
__global__ void reduce_kernel(float* __restrict__ out) {
    int idx4 = blockIdx.x * blockDim.x + threadIdx.x;   // 0 .. 65535
    float4 s = make_float4(0.f, 0.f, 0.f, 0.f);
    #pragma unroll
    for (int sp = 0; sp < KSPLIT; sp++) {
        float4 v = reinterpret_cast<const float4*>(g_Yp[sp])[idx4];
        s.x += v.x; s.y += v.y; s.z += v.z; s.w += v.w;
    }
    reinterpret_cast<float4*>(out)[idx4] = s;
}

// ---------------------------------------------------------------------------
extern "C" void kernel_launch(void* const* d_in, const int* in_sizes, int n_in,
                              void* d_out, int out_size) {
    const float* x      = (const float*)d_in[0];   // [32, 8192] fp32
    const int*   w      = (const int*)d_in[1];     // [8192, 8192] int32 (int8-valued)
    const float* scaler = (const float*)d_in[2];   // [1] fp32
    float* out = (float*)d_out;                    // [32, 8192] fp32

    static bool attr_set = false;
    if (!attr_set) {
        cudaFuncSetAttribute(gemm_kernel,
                             cudaFuncAttributeMaxDynamicSharedMemorySize, SMEM_BYTES);
        attr_set = true;
    }

    prep_pack_kernel<<<256, 256>>>(x, scaler);
    gemm_kernel<<<dim3(NSTRIPS, KSPLIT), 256, SMEM_BYTES>>>(w);
    reduce_kernel<<<128, 512>>>(out);
}

// round 17
// speedup vs baseline: 1.4752x; 1.0786x over previous
#include <cuda_runtime.h>
#include <cuda_fp16.h>
#include <cstdint>

// Problem dims
#define K_DIM 8192
#define N_DIM 8192
#define OUT_ELEMS (32 * N_DIM)

// GEMM tiling (R11-best shape)
#define KSPLIT 4
#define KCHUNK (K_DIM / KSPLIT)          // 2048
#define NKSTEPS (KCHUNK / 16)            // 128 k-steps of 16
#define CTA_N 128
#define NSTRIPS (N_DIM / CTA_N)          // 64
#define WARPS 8
#define WARP_N 16                        // 2 n-tiles of 8 per warp
#define STAGES 6                         // paired k-steps: 2 consumed per barrier

// Shared-memory stage layout
#define W_ROW_BYTES (CTA_N * 4)                  // 512
#define W_ROW_STRIDE (W_ROW_BYTES + 16)          // 528 (pad -> conflict-free frag LDS)
#define W_STAGE_BYTES (16 * W_ROW_STRIDE)        // 8448
#define A_STAGE_BYTES 1024                       // 2 t-tiles * 32 lanes * 16B
#define STAGE_BYTES (W_STAGE_BYTES + A_STAGE_BYTES)  // 9472
#define SMEM_BYTES (STAGES * STAGE_BYTES)        // 56832 (dynamic)

// Scratch (allocation-free: __device__ globals)
__device__ __align__(16) __half g_Apack[32 * K_DIM];     // 512 KB, fragment-packed A

// ---------------------------------------------------------------------------
// Kernel 1: blocks [0,256): fold scaler into x, fp16, fragment-pack A.
//           blocks [256,320): zero-init out (poisoned by harness).
// ---------------------------------------------------------------------------
__global__ void prep_pack_kernel(const float* __restrict__ x,
                                 const float* __restrict__ scaler,
                                 float* __restrict__ out) {
    if (blockIdx.x >= 256) {
        // zero 1 MB of out: 64 blocks * 256 threads * 4 float4 = 262144 floats
        int i = (blockIdx.x - 256) * 256 + threadIdx.x;   // 0 .. 16383
        float4 z = make_float4(0.f, 0.f, 0.f, 0.f);
        #pragma unroll
        for (int j = 0; j < 4; j++)
            reinterpret_cast<float4*>(out)[i + j * 16384] = z;
        return;
    }
    int L8 = blockIdx.x * blockDim.x + threadIdx.x;  // 0 .. 65535
    float s = scaler[0];
    int line = L8 >> 1;
    int half = L8 & 1;
    int ks   = line >> 6;
    int rem  = line & 63;
    int t    = rem >> 5;
    int lane = rem & 31;
    int g  = lane >> 2;
    int tg = lane & 3;
    int r0 = t * 16 + g;
    int k  = ks * 16 + tg * 2 + half * 8;

    float2 v0 = *reinterpret_cast<const float2*>(&x[(size_t)r0 * K_DIM + k]);
    float2 v1 = *reinterpret_cast<const float2*>(&x[(size_t)(r0 + 8) * K_DIM + k]);
    __half2 h0 = __floats2half2_rn(v0.x * s, v0.y * s);   // low = even k
    __half2 h1 = __floats2half2_rn(v1.x * s, v1.y * s);

    uint2 o;
    o.x = *reinterpret_cast<unsigned*>(&h0);
    o.y = *reinterpret_cast<unsigned*>(&h1);
    reinterpret_cast<uint2*>(g_Apack)[L8] = o;
}

// ---------------------------------------------------------------------------
// Kernel 2: cp.async-pipelined fused dequant GEMM (mma m16n8k16 f16.f32).
// CTA: 128 n-cols, 8 warps (warp_n = 16, m = 32). 6-stage pipeline,
// 2 k-steps consumed per barrier. Epilogue: REDG atomics straight into out.
// ---------------------------------------------------------------------------
__global__ __launch_bounds__(256, 2) void gemm_kernel(const int* __restrict__ W,
                                                      float* __restrict__ out) {
    extern __shared__ __align__(16) char sm[];

    const int tid  = threadIdx.x;
    const int lane = tid & 31;
    const int warp = tid >> 5;
    const int g    = lane >> 2;
    const int tg   = lane & 3;

    const int n0cta = blockIdx.x * CTA_N;
    const int krow0 = blockIdx.y * KCHUNK;     // first k row of this split
    const int ks0   = blockIdx.y * NKSTEPS;    // first global kstep (for A pack)

    // cp.async thread coords: each thread copies two 16B W granules;
    // threads [0,64) also copy one 16B A granule.
    const int r0  = tid >> 5;                  // W tile row 0..7 (and +8)
    const int c16 = tid & 31;                  // 16B column granule within row
    const char* wsrc0 = (const char*)(W + (size_t)(krow0 + r0) * N_DIM + n0cta + c16 * 4);
    const char* asrc0 = (const char*)g_Apack + (size_t)ks0 * A_STAGE_BYTES + tid * 16;
    const unsigned sm_base = (unsigned)__cvta_generic_to_shared(sm);

    auto issue_stage = [&](int p) {
        if (p < NKSTEPS) {
            unsigned d  = sm_base + (p % STAGES) * STAGE_BYTES;
            const char* ws = wsrc0 + (size_t)p * 16 * N_DIM * 4;
            unsigned d0 = d + r0 * W_ROW_STRIDE + c16 * 16;
            asm volatile("cp.async.cg.shared.global [%0], [%1], 16;\n"
                         :: "r"(d0), "l"(ws));
            asm volatile("cp.async.cg.shared.global [%0], [%1], 16;\n"
                         :: "r"(d0 + 8 * W_ROW_STRIDE), "l"(ws + (size_t)8 * N_DIM * 4));
            if (tid < 64) {
                asm volatile("cp.async.ca.shared.global [%0], [%1], 16;\n"
                             :: "r"(d + W_STAGE_BYTES + tid * 16),
                                "l"(asrc0 + (size_t)p * A_STAGE_BYTES));
            }
        }
        asm volatile("cp.async.commit_group;\n" ::);
    };

    issue_stage(0);
    issue_stage(1);
    issue_stage(2);
    issue_stage(3);

    float acc[2][2][4] = {};

    auto consume = [&](int ks) {
        const unsigned sb = sm_base + (ks % STAGES) * STAGE_BYTES;

        // A fragments: 2 x LDS.128 (broadcast across warps)
        unsigned a[2][4];
        const unsigned ab = sb + W_STAGE_BYTES + lane * 16;
        #pragma unroll
        for (int t = 0; t < 2; t++) {
            asm volatile("ld.shared.v4.b32 {%0,%1,%2,%3}, [%4];"
                         : "=r"(a[t][0]), "=r"(a[t][1]), "=r"(a[t][2]), "=r"(a[t][3])
                         : "r"(ab + t * 512));
        }

        #pragma unroll
        for (int i = 0; i < 2; i++) {
            // B ints from smem: rows tg*2 + {0,1,8,9}, col warp*16 + i*8 + g.
            // Row stride 528B -> bank = 8*tg + g (+const) : conflict-free.
            const unsigned wb = sb + (tg * 2) * W_ROW_STRIDE + (warp * WARP_N + i * 8 + g) * 4;
            int w0, w1, w2, w3;
            asm volatile("ld.shared.b32 %0, [%1];" : "=r"(w0) : "r"(wb));
            asm volatile("ld.shared.b32 %0, [%1];" : "=r"(w1) : "r"(wb + W_ROW_STRIDE));
            asm volatile("ld.shared.b32 %0, [%1];" : "=r"(w2) : "r"(wb + 8 * W_ROW_STRIDE));
            asm volatile("ld.shared.b32 %0, [%1];" : "=r"(w3) : "r"(wb + 9 * W_ROW_STRIDE));
            __half2 p0 = __floats2half2_rn((float)w0, (float)w1);   // low = even k
            __half2 p1 = __floats2half2_rn((float)w2, (float)w3);
            unsigned b0 = *reinterpret_cast<unsigned*>(&p0);
            unsigned b1 = *reinterpret_cast<unsigned*>(&p1);

            #pragma unroll
            for (int t = 0; t < 2; t++) {
                float* c = acc[t][i];
                asm volatile(
                    "mma.sync.aligned.m16n8k16.row.col.f32.f16.f16.f32 "
                    "{%0,%1,%2,%3}, {%4,%5,%6,%7}, {%8,%9}, {%0,%1,%2,%3};"
                    : "+f"(c[0]), "+f"(c[1]), "+f"(c[2]), "+f"(c[3])
                    : "r"(a[t][0]), "r"(a[t][1]), "r"(a[t][2]), "r"(a[t][3]),
                      "r"(b0), "r"(b1));
            }
        }
    };

    for (int ks = 0; ks < NKSTEPS; ks += 2) {
        // Need stages ks, ks+1 complete; 2 newer groups may stay in flight.
        asm volatile("cp.async.wait_group 2;\n" ::);
        __syncthreads();
        issue_stage(ks + 4);
        issue_stage(ks + 5);
        consume(ks);
        consume(ks + 1);
    }

    // Epilogue: accumulate k-split partial straight into out via REDG (no return).
    #pragma unroll
    for (int t = 0; t < 2; t++) {
        #pragma unroll
        for (int i = 0; i < 2; i++) {
            const int row = t * 16 + g;
            const int col = n0cta + warp * WARP_N + i * 8 + tg * 2;
            float* p0 = &out[(size_t)row * N_DIM + col];
            float* p1 = &out[(size_t)(row + 8) * N_DIM + col];
            asm volatile("red.global.add.f32 [%0], %1;" :: "l"(p0),     "f"(acc[t][i][0]) : "memory");
            asm volatile("red.global.add.f32 [%0], %1;" :: "l"(p0 + 1), "f"(acc[t][i][1]) : "memory");
            asm volatile("red.global.add.f32 [%0], %1;" :: "l"(p1),     "f"(acc[t][i][2]) : "memory");
            asm volatile("red.global.add.f32 [%0], %1;" :: "l"(p1 + 1), "f"(acc[t][i][3]) : "memory");
        }
    }
}

// ---------------------------------------------------------------------------
extern "C" void kernel_launch(void* const* d_in, const int* in_sizes, int n_in,
                              void* d_out, int out_size) {
    const float* x      = (const float*)d_in[0];   // [32, 8192] fp32
    const int*   w      = (const int*)d_in[1];     // [8192, 8192] int32 (int8-valued)
    const float* scaler = (const float*)d_in[2];   // [1] fp32
    float* out = (float*)d_out;                    // [32, 8192] fp32

    static bool attr_set = false;
    if (!attr_set) {
        cudaFuncSetAttribute(gemm_kernel,
                             cudaFuncAttributeMaxDynamicSharedMemorySize, SMEM_BYTES);
        attr_set = true;
    }

    prep_pack_kernel<<<320, 256>>>(x, scaler, out);
    gemm_kernel<<<dim3(NSTRIPS, KSPLIT), 256, SMEM_BYTES>>>(w, out);
}